// round 14
// baseline (speedup 1.0000x reference)
#include <cuda_runtime.h>
#include <cuda_bf16.h>
#include <math.h>
#include <stdint.h>

// Problem constants
constexpr int B_  = 8;
constexpr int P_  = 196;
constexpr int T_  = 64;
constexpr int H_  = 768;
constexpr int MD  = 2048;
constexpr int BP  = B_ * P_;   // 1568
constexpr int BT  = B_ * T_;   // 512
constexpr int NCH = MD / 64;   // 32 K-chunks of 64

// ---------------------------------------------------------------------------
// Scratch (device globals; no allocation allowed)
// ---------------------------------------------------------------------------
__device__ float g_mlo[BP * H_];
__device__ float g_sc[BT * P_];            // raw scores scratch
__device__ __align__(16) __nv_bfloat16 g_a_hi[BP * MD],  g_a_lo[BP * MD];
__device__ __align__(16) __nv_bfloat16 g_wm_hi[H_ * MD], g_wm_lo[H_ * MD];
__device__ __align__(16) __nv_bfloat16 g_wf_hi[H_ * MD], g_wf_lo[H_ * MD];
__device__ __align__(16) __nv_bfloat16 g_cx_hi[BT * MD], g_cx_lo[BT * MD];

// ---------------------------------------------------------------------------
// PTX helpers
// ---------------------------------------------------------------------------
__device__ __forceinline__ uint32_t smem_u32(const void* p) {
    uint32_t a;
    asm("{ .reg .u64 t; cvta.to.shared.u64 t, %1; cvt.u32.u64 %0, t; }"
        : "=r"(a) : "l"(p));
    return a;
}
__device__ __forceinline__ uint32_t swz(uint32_t o) { return o ^ ((o >> 3) & 0x70); }

__device__ __forceinline__ void cp16(uint32_t dst, const void* src, int srcsz) {
    asm volatile("cp.async.cg.shared.global [%0], [%1], 16, %2;"
                 :: "r"(dst), "l"(src), "r"(srcsz));
}
__device__ __forceinline__ void ldsm_x4(uint32_t& r0, uint32_t& r1, uint32_t& r2,
                                        uint32_t& r3, uint32_t a) {
    asm volatile("ldmatrix.sync.aligned.m8n8.x4.shared.b16 {%0,%1,%2,%3}, [%4];"
                 : "=r"(r0), "=r"(r1), "=r"(r2), "=r"(r3) : "r"(a));
}
__device__ __forceinline__ void mma16816(float c[4], const uint32_t a[4],
                                         const uint32_t b[2]) {
    asm volatile("mma.sync.aligned.m16n8k16.row.col.f32.bf16.bf16.f32 "
                 "{%0,%1,%2,%3}, {%4,%5,%6,%7}, {%8,%9}, {%0,%1,%2,%3};"
                 : "+f"(c[0]), "+f"(c[1]), "+f"(c[2]), "+f"(c[3])
                 : "r"(a[0]), "r"(a[1]), "r"(a[2]), "r"(a[3]),
                   "r"(b[0]), "r"(b[1]));
}

// f32x2 helpers (ctx kernel)
__device__ __forceinline__ unsigned long long ffma2(unsigned long long a,
                                                    unsigned long long b,
                                                    unsigned long long c) {
    unsigned long long d;
    asm("fma.rn.f32x2 %0, %1, %2, %3;" : "=l"(d) : "l"(a), "l"(b), "l"(c));
    return d;
}
__device__ __forceinline__ float2 unpack2(unsigned long long v) {
    float2 f;
    asm("mov.b64 {%0, %1}, %2;" : "=f"(f.x), "=f"(f.y) : "l"(v));
    return f;
}

// convert one float4 -> packed bf16x2 pair (hi, lo)
__device__ __forceinline__ void split4(float4 v, uint2& uh, uint2& ul) {
    __nv_bfloat16 h0 = __float2bfloat16(v.x), h1 = __float2bfloat16(v.y);
    __nv_bfloat16 h2 = __float2bfloat16(v.z), h3 = __float2bfloat16(v.w);
    __nv_bfloat16 l0 = __float2bfloat16(v.x - __bfloat162float(h0));
    __nv_bfloat16 l1 = __float2bfloat16(v.y - __bfloat162float(h1));
    __nv_bfloat16 l2 = __float2bfloat16(v.z - __bfloat162float(h2));
    __nv_bfloat16 l3 = __float2bfloat16(v.w - __bfloat162float(h3));
    __nv_bfloat162 ha = __halves2bfloat162(h0, h1), hb = __halves2bfloat162(h2, h3);
    __nv_bfloat162 la = __halves2bfloat162(l0, l1), lb = __halves2bfloat162(l2, l3);
    uh.x = *(uint32_t*)&ha; uh.y = *(uint32_t*)&hb;
    ul.x = *(uint32_t*)&la; ul.y = *(uint32_t*)&lb;
}

// ---------------------------------------------------------------------------
// Fused fp32 -> (bf16 hi, bf16 lo) split conversion for all three tensors.
// Each thread handles 2 float4 (32 B) -> one STG.128 for hi + one for lo.
// ---------------------------------------------------------------------------
constexpr int N8_A = BP * MD / 8;     // 401408
constexpr int N8_W = H_ * MD / 8;     // 196608
constexpr int N8_TOT = N8_A + 2 * N8_W;

__global__ void convert_split_all(const float4* __restrict__ sA,
                                  const float4* __restrict__ sWm,
                                  const float4* __restrict__ sWf,
                                  uint4* __restrict__ aH, uint4* __restrict__ aL,
                                  uint4* __restrict__ wmH, uint4* __restrict__ wmL,
                                  uint4* __restrict__ wfH, uint4* __restrict__ wfL)
{
    int i = blockIdx.x * 256 + threadIdx.x;
    if (i >= N8_TOT) return;
    const float4* src;
    uint4 *hi, *lo;
    int j;
    if (i < N8_A)              { src = sA;  hi = aH;  lo = aL;  j = i; }
    else if (i < N8_A + N8_W)  { src = sWm; hi = wmH; lo = wmL; j = i - N8_A; }
    else                       { src = sWf; hi = wfH; lo = wfL; j = i - N8_A - N8_W; }
    float4 v0 = src[2 * j], v1 = src[2 * j + 1];
    uint2 h0, l0, h1, l1;
    split4(v0, h0, l0);
    split4(v1, h1, l1);
    uint4 uh, ul;
    uh.x = h0.x; uh.y = h0.y; uh.z = h1.x; uh.w = h1.y;
    ul.x = l0.x; ul.y = l0.y; ul.z = l1.x; ul.w = l1.y;
    hi[j] = uh;
    lo[j] = ul;
}

// ---------------------------------------------------------------------------
// mma.sync split-bf16 TN GEMM, NST-stage cp.async pipeline. (frozen, R13-best)
// ---------------------------------------------------------------------------
template<int MT, int NT, int NWM, int MINB, int NST>
__global__ void __launch_bounds__(256, MINB)
gemm_mma_bf16x3(const __nv_bfloat16* __restrict__ aHi, const __nv_bfloat16* __restrict__ aLo,
                const __nv_bfloat16* __restrict__ wHi, const __nv_bfloat16* __restrict__ wLo,
                const float* __restrict__ bias, const float* __restrict__ addin,
                float* __restrict__ C, int M)
{
    constexpr int NWN = 8 / NWM;
    constexpr int BM  = NWM * MT * 16;
    constexpr int BN  = NWN * NT * 8;
    constexpr int A_B = BM * 128;
    constexpr int W_B = BN * 128;
    constexpr int STG = 2 * A_B + 2 * W_B;

    extern __shared__ __align__(1024) char smem[];
    const uint32_t sb = smem_u32(smem);
    const int tid = threadIdx.x, lane = tid & 31, wid = tid >> 5;
    const int wm = wid / NWN, wn = wid % NWN;
    const int m0 = blockIdx.x * BM, n0 = blockIdx.y * BN;

    auto stage = [&](int c) {
        const uint32_t base = sb + (c % NST) * STG;
        const int kt = c * 64;
        #pragma unroll
        for (int l = 0; l < BM * 8 / 256; l++) {
            int idx = tid + l * 256;
            int r = idx >> 3, cc = idx & 7;
            uint32_t so = swz((uint32_t)(r * 128 + cc * 16));
            int row = m0 + r;
            int sz  = (row < M) ? 16 : 0;
            size_t off = (size_t)(sz ? row : 0) * MD + kt + cc * 8;
            cp16(base + so,       aHi + off, sz);
            cp16(base + A_B + so, aLo + off, sz);
        }
        #pragma unroll
        for (int l = 0; l < BN * 8 / 256; l++) {
            int idx = tid + l * 256;
            int r = idx >> 3, cc = idx & 7;
            uint32_t so = swz((uint32_t)(r * 128 + cc * 16));
            size_t off = (size_t)(n0 + r) * MD + kt + cc * 8;
            cp16(base + 2 * A_B + so,       wHi + off, 16);
            cp16(base + 2 * A_B + W_B + so, wLo + off, 16);
        }
        asm volatile("cp.async.commit_group;" ::: "memory");
    };

    float acc[MT][NT][4];
    #pragma unroll
    for (int i = 0; i < MT; i++)
        #pragma unroll
        for (int j = 0; j < NT; j++)
            #pragma unroll
            for (int q = 0; q < 4; q++) acc[i][j][q] = 0.f;

    #pragma unroll
    for (int s = 0; s < NST; s++) stage(s);

    for (int c = 0; c < NCH; c++) {
        asm volatile("cp.async.wait_group %0;" :: "n"(NST - 1) : "memory");
        __syncthreads();
        const uint32_t base = sb + (c % NST) * STG;
        const uint32_t Ah = base, Al = base + A_B;
        const uint32_t Wh = base + 2 * A_B, Wl = Wh + W_B;

        #pragma unroll
        for (int ks = 0; ks < 4; ks++) {
            uint32_t bh[NT][2], bl[NT][2];
            #pragma unroll
            for (int ntp = 0; ntp < NT / 2; ntp++) {
                uint32_t so = swz((uint32_t)((wn * (NT * 8) + ntp * 16
                                              + ((lane >> 4) & 1) * 8 + (lane & 7)) * 128
                                             + ks * 32 + ((lane >> 3) & 1) * 16));
                ldsm_x4(bh[2 * ntp][0], bh[2 * ntp][1],
                        bh[2 * ntp + 1][0], bh[2 * ntp + 1][1], Wh + so);
                ldsm_x4(bl[2 * ntp][0], bl[2 * ntp][1],
                        bl[2 * ntp + 1][0], bl[2 * ntp + 1][1], Wl + so);
            }
            uint32_t ah[MT][4], al[MT][4];
            #pragma unroll
            for (int mt = 0; mt < MT; mt++) {
                uint32_t so = swz((uint32_t)((wm * (MT * 16) + mt * 16 + (lane & 15)) * 128
                                             + ks * 32 + (lane >> 4) * 16));
                ldsm_x4(ah[mt][0], ah[mt][1], ah[mt][2], ah[mt][3], Ah + so);
                ldsm_x4(al[mt][0], al[mt][1], al[mt][2], al[mt][3], Al + so);
            }
            #pragma unroll
            for (int mt = 0; mt < MT; mt++)
                #pragma unroll
                for (int nt = 0; nt < NT; nt++)
                    mma16816(acc[mt][nt], ah[mt], bh[nt]);
            #pragma unroll
            for (int mt = 0; mt < MT; mt++)
                #pragma unroll
                for (int nt = 0; nt < NT; nt++)
                    mma16816(acc[mt][nt], ah[mt], bl[nt]);
            #pragma unroll
            for (int mt = 0; mt < MT; mt++)
                #pragma unroll
                for (int nt = 0; nt < NT; nt++)
                    mma16816(acc[mt][nt], al[mt], bh[nt]);
        }
        __syncthreads();
        if (c + NST < NCH) stage(c + NST);
        else asm volatile("cp.async.commit_group;" ::: "memory");
    }
    asm volatile("cp.async.wait_group 0;" ::: "memory");

    #pragma unroll
    for (int mt = 0; mt < MT; mt++) {
        #pragma unroll
        for (int half = 0; half < 2; half++) {
            int row = m0 + wm * (MT * 16) + mt * 16 + half * 8 + (lane >> 2);
            if (row >= M) continue;
            #pragma unroll
            for (int nt = 0; nt < NT; nt++) {
                int col = n0 + wn * (NT * 8) + nt * 8 + (lane & 3) * 2;
                float2 v;
                v.x = acc[mt][nt][half * 2 + 0];
                v.y = acc[mt][nt][half * 2 + 1];
                float2 bv = *(const float2*)(bias + col);
                v.x += bv.x; v.y += bv.y;
                if (addin) {
                    float2 h = *(const float2*)(addin + (size_t)row * H_ + col);
                    v.x += h.x; v.y += h.y;
                }
                *(float2*)(C + (size_t)row * H_ + col) = v;
            }
        }
    }
}

// ---------------------------------------------------------------------------
// scores: raw scores, mlo read exactly once. 16-t tiles -> 224 blocks.
// ---------------------------------------------------------------------------
constexpr int SC_TG = 16;

__global__ void __launch_bounds__(256)
scores_kernel(const float* __restrict__ mlo, const float* __restrict__ hiddens,
              const float* __restrict__ W_rect, float* __restrict__ sc)
{
    extern __shared__ __align__(16) float s_hid[];    // [SC_TG][H_] = 48 KB

    const int pt = blockIdx.x;          // 0..6
    const int t0 = blockIdx.y * SC_TG;  // 0,16,32,48
    const int b  = blockIdx.z;
    const int tid = threadIdx.x, lane = tid & 31, warp = tid >> 5;

    {
        const float4* src = (const float4*)(hiddens + (size_t)(b * T_ + t0) * H_);
        float4* dst = (float4*)s_hid;
        for (int i = tid; i < SC_TG * H_ / 4; i += 256) dst[i] = src[i];
    }

    float4 wr[6];
    #pragma unroll
    for (int q = 0; q < 6; q++) wr[q] = ((const float4*)W_rect)[q * 32 + lane];

    const int nrows = (warp < 4) ? 4 : 3;
    float4 x[4][6];
    #pragma unroll
    for (int r = 0; r < 4; r++) {
        if (r >= nrows) break;
        const int p = pt * 28 + warp + r * 8;
        const float4* mp = (const float4*)(mlo + (size_t)(b * P_ + p) * H_);
        #pragma unroll
        for (int q = 0; q < 6; q++) x[r][q] = mp[q * 32 + lane];
    }
    __syncthreads();

    for (int t = 0; t < SC_TG; t++) {
        float4 hd[6];
        const float4* hp = (const float4*)(s_hid + t * H_);
        #pragma unroll
        for (int q = 0; q < 6; q++) hd[q] = hp[q * 32 + lane];

        float acc[4] = {};
        #pragma unroll
        for (int r = 0; r < 4; r++) {
            if (r >= nrows) break;
            float a = 0.f;
            #pragma unroll
            for (int q = 0; q < 6; q++) {
                a += fmaxf(x[r][q].x + hd[q].x, 0.f) * wr[q].x
                   + fmaxf(x[r][q].y + hd[q].y, 0.f) * wr[q].y
                   + fmaxf(x[r][q].z + hd[q].z, 0.f) * wr[q].z
                   + fmaxf(x[r][q].w + hd[q].w, 0.f) * wr[q].w;
            }
            acc[r] = a;
        }
        #pragma unroll
        for (int r = 0; r < 4; r++) {
            if (r >= nrows) break;
            float v = acc[r];
            #pragma unroll
            for (int o = 16; o > 0; o >>= 1) v += __shfl_xor_sync(0xffffffffu, v, o);
            if (lane == 0)
                sc[(size_t)(b * T_ + t0 + t) * P_ + pt * 28 + warp + r * 8] = v;
        }
    }
}

// ---------------------------------------------------------------------------
// ctx + fused softmax, t-split across 2 CTAs (32 t each).
// fm chunks shrunk to 16 rows (8 KB) -> CTA smem 69.7 KB -> 3 CTAs/SM.
// ---------------------------------------------------------------------------
constexpr int AT_F2    = 34;                          // float2 units per p-row (pad)
constexpr int AT_BYTES = P_ * AT_F2 * 8;              // 53,312
constexpr int FM_ROWS  = 16;
constexpr int FM_CHUNK = FM_ROWS * 128 * 4;           // 8 KB
constexpr int NCHC     = 13;                          // 12*16 + 4 = 196
constexpr int CTX_SMEM = AT_BYTES + 2 * FM_CHUNK;     // 69,696

__global__ void __launch_bounds__(256, 3)
ctx_kernel(const float* __restrict__ sc, const float* __restrict__ fm,
           __nv_bfloat16* __restrict__ cxh, __nv_bfloat16* __restrict__ cxl,
           float* __restrict__ attn_out)
{
    extern __shared__ __align__(16) char smem[];
    float2* s_at2 = (float2*)smem;
    const uint32_t fm_base = smem_u32(smem) + AT_BYTES;

    const int m0 = blockIdx.x * 128;
    const int th = blockIdx.y;          // t-half: 0 or 1
    const int b  = blockIdx.z;
    const int tid = threadIdx.x;
    const int tx = tid & 31;            // lane: 4 m cols
    const int ty = tid >> 5;            // warp: 4 t's

    const float* fmb = fm + (size_t)b * P_ * MD + m0;
    auto stage = [&](int ch) {
        const int rows = (ch == NCHC - 1) ? 4 : FM_ROWS;
        const uint32_t base = fm_base + (ch & 1) * FM_CHUNK;
        for (int i = tid; i < rows * 32; i += 256) {
            int r = i >> 5, c = i & 31;
            cp16(base + r * 512 + c * 16,
                 fmb + (size_t)(ch * FM_ROWS + r) * MD + c * 4, 16);
        }
        asm volatile("cp.async.commit_group;" ::: "memory");
    };

    stage(0);
    stage(1);

    // fused softmax for this CTA's 32 t's (hides the cp.async DRAM latency)
    #pragma unroll
    for (int j = 0; j < 4; j++) {
        const int tl = ty * 4 + j;                 // local t 0..31
        const int tg = th * 32 + tl;               // global t
        const float* sp = sc + (size_t)(b * T_ + tg) * P_;
        float v[7];
        float mx = -1e30f;
        #pragma unroll
        for (int i = 0; i < 7; i++) {
            int p = tx + i * 32;
            v[i] = (p < P_) ? sp[p] : -1e30f;
            mx = fmaxf(mx, v[i]);
        }
        #pragma unroll
        for (int o = 16; o > 0; o >>= 1) mx = fmaxf(mx, __shfl_xor_sync(0xffffffffu, mx, o));
        float sm = 0.f;
        #pragma unroll
        for (int i = 0; i < 7; i++) {
            v[i] = __expf(v[i] - mx);
            sm += v[i];
        }
        #pragma unroll
        for (int o = 16; o > 0; o >>= 1) sm += __shfl_xor_sync(0xffffffffu, sm, o);
        float inv = 1.f / sm;
        #pragma unroll
        for (int i = 0; i < 7; i++) {
            int p = tx + i * 32;
            if (p < P_) {
                float a = v[i] * inv;
                s_at2[p * AT_F2 + tl] = make_float2(a, a);
                if (attn_out != nullptr && m0 == 0)
                    attn_out[(size_t)(b * T_ + tg) * P_ + p] = a;
            }
        }
    }
    __syncthreads();

    unsigned long long acc[4][2] = {};

    auto body = [&](const float* sf, int r, int pbase) {
        const int p = pbase + r;
        float4 fv = *(const float4*)(sf + r * 128 + tx * 4);
        unsigned long long f0 = *(unsigned long long*)&fv.x;
        unsigned long long f1 = *(unsigned long long*)&fv.z;
        const float4* ap = (const float4*)(s_at2 + p * AT_F2 + ty * 4);
        float4 a01 = ap[0], a23 = ap[1];
        unsigned long long av0 = *(unsigned long long*)&a01.x;
        unsigned long long av1 = *(unsigned long long*)&a01.z;
        unsigned long long av2 = *(unsigned long long*)&a23.x;
        unsigned long long av3 = *(unsigned long long*)&a23.z;
        acc[0][0] = ffma2(av0, f0, acc[0][0]);
        acc[0][1] = ffma2(av0, f1, acc[0][1]);
        acc[1][0] = ffma2(av1, f0, acc[1][0]);
        acc[1][1] = ffma2(av1, f1, acc[1][1]);
        acc[2][0] = ffma2(av2, f0, acc[2][0]);
        acc[2][1] = ffma2(av2, f1, acc[2][1]);
        acc[3][0] = ffma2(av3, f0, acc[3][0]);
        acc[3][1] = ffma2(av3, f1, acc[3][1]);
    };

    for (int ch = 0; ch < NCHC; ch++) {
        asm volatile("cp.async.wait_group 1;" ::: "memory");
        __syncthreads();
        const float* sf = (const float*)(smem + AT_BYTES + (ch & 1) * FM_CHUNK);
        if (ch < NCHC - 1) {
            #pragma unroll 4
            for (int r = 0; r < FM_ROWS; r++) body(sf, r, ch * FM_ROWS);
        } else {
            #pragma unroll
            for (int r = 0; r < 4; r++) body(sf, r, ch * FM_ROWS);
        }
        __syncthreads();
        if (ch + 2 < NCHC) stage(ch + 2);
        else asm volatile("cp.async.commit_group;" ::: "memory");
    }
    asm volatile("cp.async.wait_group 0;" ::: "memory");

    #pragma unroll
    for (int i = 0; i < 4; i++) {
        float2 c01 = unpack2(acc[i][0]);
        float2 c23 = unpack2(acc[i][1]);
        float4 v4 = make_float4(c01.x, c01.y, c23.x, c23.y);
        uint2 uh, ul;
        split4(v4, uh, ul);
        size_t off = (size_t)(b * T_ + th * 32 + ty * 4 + i) * MD + m0 + tx * 4;
        *(uint2*)(cxh + off) = uh;
        *(uint2*)(cxl + off) = ul;
    }
}

// ---------------------------------------------------------------------------
// launch
// ---------------------------------------------------------------------------
extern "C" void kernel_launch(void* const* d_in, const int* in_sizes, int n_in,
                              void* d_out, int out_size)
{
    const float* maps    = (const float*)d_in[0];
    const float* hiddens = (const float*)d_in[1];
    const float* W_map   = (const float*)d_in[2];
    const float* b_map   = (const float*)d_in[3];
    const float* W_final = (const float*)d_in[4];
    const float* b_final = (const float*)d_in[5];
    const float* W_rect  = (const float*)d_in[6];
    // d_in[7] = b_rect : softmax-invariant, unused.

    float* out = (float*)d_out;       // [out (BT,H) | attn (BT,P)]

    void *v0, *v1, *v2, *v3, *v4, *v5, *v6, *v7, *v8, *v9;
    cudaGetSymbolAddress(&v0, g_mlo);
    cudaGetSymbolAddress(&v1, g_sc);
    cudaGetSymbolAddress(&v2, g_a_hi);  cudaGetSymbolAddress(&v3, g_a_lo);
    cudaGetSymbolAddress(&v4, g_wm_hi); cudaGetSymbolAddress(&v5, g_wm_lo);
    cudaGetSymbolAddress(&v6, g_wf_hi); cudaGetSymbolAddress(&v7, g_wf_lo);
    cudaGetSymbolAddress(&v8, g_cx_hi); cudaGetSymbolAddress(&v9, g_cx_lo);
    float* p_mlo = (float*)v0;
    float* p_sc  = (float*)v1;
    __nv_bfloat16 *aHi = (__nv_bfloat16*)v2, *aLo = (__nv_bfloat16*)v3;
    __nv_bfloat16 *wmHi = (__nv_bfloat16*)v4, *wmLo = (__nv_bfloat16*)v5;
    __nv_bfloat16 *wfHi = (__nv_bfloat16*)v6, *wfLo = (__nv_bfloat16*)v7;
    __nv_bfloat16 *cxHi = (__nv_bfloat16*)v8, *cxLo = (__nv_bfloat16*)v9;

    float* attn = (out_size >= BT * H_ + BT * P_) ? out + (size_t)BT * H_ : nullptr;

    // GEMM1: MT=2, NT=2, NWM=2 -> BM=64, BN=64, 2-stage, 64 KB, 3 CTAs/SM.
    // GEMM4: MT=1, NT=2, NWM=4 -> BM=64, BN=32, 2-stage, 48 KB, 3 CTAs/SM.
    constexpr int SMEM_G1 = 2 * (2 * 64 * 128 + 2 * 64 * 128);   // 65536
    constexpr int SMEM_G4 = 2 * (2 * 64 * 128 + 2 * 32 * 128);   // 49152
    constexpr int SMEM_SC = SC_TG * H_ * 4;                      // 49152
    cudaFuncSetAttribute((const void*)gemm_mma_bf16x3<2, 2, 2, 3, 2>,
                         cudaFuncAttributeMaxDynamicSharedMemorySize, SMEM_G1);
    cudaFuncSetAttribute((const void*)gemm_mma_bf16x3<1, 2, 4, 3, 2>,
                         cudaFuncAttributeMaxDynamicSharedMemorySize, SMEM_G4);
    cudaFuncSetAttribute(scores_kernel,
                         cudaFuncAttributeMaxDynamicSharedMemorySize, SMEM_SC);
    cudaFuncSetAttribute(ctx_kernel,
                         cudaFuncAttributeMaxDynamicSharedMemorySize, CTX_SMEM);

    // 1. fused split-convert (2 float4 per thread, STG.128 epilogue)
    convert_split_all<<<(N8_TOT + 255) / 256, 256>>>(
        (const float4*)maps, (const float4*)W_map, (const float4*)W_final,
        (uint4*)aHi, (uint4*)aLo,
        (uint4*)wmHi, (uint4*)wmLo,
        (uint4*)wfHi, (uint4*)wfLo);

    // 2. mlo = maps @ W_map^T + b_map   (25 x 12 = 300 blocks, 3 CTAs/SM)
    gemm_mma_bf16x3<2, 2, 2, 3, 2><<<dim3((BP + 63) / 64, H_ / 64), 256, SMEM_G1>>>(
        aHi, aLo, wmHi, wmLo, b_map, nullptr, p_mlo, BP);

    // 3. raw scores (7 x 4 x 8 = 224 blocks)
    scores_kernel<<<dim3(7, 4, B_), 256, SMEM_SC>>>(p_mlo, hiddens, W_rect, p_sc);

    // 4. softmax + ctx fused (16 x 2 x 8 = 256 blocks, 3 CTAs/SM)
    ctx_kernel<<<dim3(MD / 128, 2, B_), 256, CTX_SMEM>>>(p_sc, maps, cxHi, cxLo, attn);

    // 5. out = ctx @ W_final^T + b_final + hiddens   (8 x 24 = 192 blocks)
    gemm_mma_bf16x3<1, 2, 4, 3, 2><<<dim3(BT / 64, H_ / 32), 256, SMEM_G4>>>(
        cxHi, cxLo, wfHi, wfLo, b_final, hiddens, out, BT);
}

// round 16
// speedup vs baseline: 1.1388x; 1.1388x over previous
#include <cuda_runtime.h>
#include <cuda_bf16.h>
#include <math.h>
#include <stdint.h>

// Problem constants
constexpr int B_  = 8;
constexpr int P_  = 196;
constexpr int T_  = 64;
constexpr int H_  = 768;
constexpr int MD  = 2048;
constexpr int BP  = B_ * P_;   // 1568
constexpr int BT  = B_ * T_;   // 512
constexpr int NCH = MD / 64;   // 32 K-chunks of 64
constexpr int KP  = 208;       // padded P for ctx MMA (13 x 16)

// ---------------------------------------------------------------------------
// Scratch (device globals; no allocation allowed)
// ---------------------------------------------------------------------------
__device__ float g_mlo[BP * H_];
__device__ float g_sc[BT * P_];            // raw scores scratch
__device__ __align__(16) __nv_bfloat16 g_a_hi[BP * MD],  g_a_lo[BP * MD];
__device__ __align__(16) __nv_bfloat16 g_wm_hi[H_ * MD], g_wm_lo[H_ * MD];
__device__ __align__(16) __nv_bfloat16 g_wf_hi[H_ * MD], g_wf_lo[H_ * MD];
__device__ __align__(16) __nv_bfloat16 g_cx_hi[BT * MD], g_cx_lo[BT * MD];
__device__ __align__(16) __nv_bfloat16 g_at_hi[BT * KP], g_at_lo[BT * KP];

// ---------------------------------------------------------------------------
// PTX helpers
// ---------------------------------------------------------------------------
__device__ __forceinline__ uint32_t smem_u32(const void* p) {
    uint32_t a;
    asm("{ .reg .u64 t; cvta.to.shared.u64 t, %1; cvt.u32.u64 %0, t; }"
        : "=r"(a) : "l"(p));
    return a;
}
__device__ __forceinline__ uint32_t swz(uint32_t o) { return o ^ ((o >> 3) & 0x70); }

__device__ __forceinline__ void cp16(uint32_t dst, const void* src, int srcsz) {
    asm volatile("cp.async.cg.shared.global [%0], [%1], 16, %2;"
                 :: "r"(dst), "l"(src), "r"(srcsz));
}
__device__ __forceinline__ void ldsm_x4(uint32_t& r0, uint32_t& r1, uint32_t& r2,
                                        uint32_t& r3, uint32_t a) {
    asm volatile("ldmatrix.sync.aligned.m8n8.x4.shared.b16 {%0,%1,%2,%3}, [%4];"
                 : "=r"(r0), "=r"(r1), "=r"(r2), "=r"(r3) : "r"(a));
}
__device__ __forceinline__ void ldsm_x4t(uint32_t& r0, uint32_t& r1, uint32_t& r2,
                                         uint32_t& r3, uint32_t a) {
    asm volatile("ldmatrix.sync.aligned.m8n8.x4.trans.shared.b16 {%0,%1,%2,%3}, [%4];"
                 : "=r"(r0), "=r"(r1), "=r"(r2), "=r"(r3) : "r"(a));
}
__device__ __forceinline__ void mma16816(float c[4], const uint32_t a[4],
                                         const uint32_t b[2]) {
    asm volatile("mma.sync.aligned.m16n8k16.row.col.f32.bf16.bf16.f32 "
                 "{%0,%1,%2,%3}, {%4,%5,%6,%7}, {%8,%9}, {%0,%1,%2,%3};"
                 : "+f"(c[0]), "+f"(c[1]), "+f"(c[2]), "+f"(c[3])
                 : "r"(a[0]), "r"(a[1]), "r"(a[2]), "r"(a[3]),
                   "r"(b[0]), "r"(b[1]));
}

// convert one float4 -> packed bf16x2 pair (hi, lo)
__device__ __forceinline__ void split4(float4 v, uint2& uh, uint2& ul) {
    __nv_bfloat16 h0 = __float2bfloat16(v.x), h1 = __float2bfloat16(v.y);
    __nv_bfloat16 h2 = __float2bfloat16(v.z), h3 = __float2bfloat16(v.w);
    __nv_bfloat16 l0 = __float2bfloat16(v.x - __bfloat162float(h0));
    __nv_bfloat16 l1 = __float2bfloat16(v.y - __bfloat162float(h1));
    __nv_bfloat16 l2 = __float2bfloat16(v.z - __bfloat162float(h2));
    __nv_bfloat16 l3 = __float2bfloat16(v.w - __bfloat162float(h3));
    __nv_bfloat162 ha = __halves2bfloat162(h0, h1), hb = __halves2bfloat162(h2, h3);
    __nv_bfloat162 la = __halves2bfloat162(l0, l1), lb = __halves2bfloat162(l2, l3);
    uh.x = *(uint32_t*)&ha; uh.y = *(uint32_t*)&hb;
    ul.x = *(uint32_t*)&la; ul.y = *(uint32_t*)&lb;
}

// ---------------------------------------------------------------------------
// Fused fp32 -> (bf16 hi, bf16 lo) split conversion (R13 version).
// ---------------------------------------------------------------------------
constexpr int N4_A = BP * MD / 4;
constexpr int N4_W = H_ * MD / 4;
constexpr int N4_TOT = N4_A + 2 * N4_W;

__global__ void convert_split_all(const float4* __restrict__ sA,
                                  const float4* __restrict__ sWm,
                                  const float4* __restrict__ sWf,
                                  uint2* __restrict__ aH, uint2* __restrict__ aL,
                                  uint2* __restrict__ wmH, uint2* __restrict__ wmL,
                                  uint2* __restrict__ wfH, uint2* __restrict__ wfL)
{
    for (int i = blockIdx.x * 256 + threadIdx.x; i < N4_TOT; i += gridDim.x * 256) {
        const float4* src;
        uint2 *hi, *lo;
        int j;
        if (i < N4_A)              { src = sA;  hi = aH;  lo = aL;  j = i; }
        else if (i < N4_A + N4_W)  { src = sWm; hi = wmH; lo = wmL; j = i - N4_A; }
        else                       { src = sWf; hi = wfH; lo = wfL; j = i - N4_A - N4_W; }
        uint2 uh, ul;
        split4(src[j], uh, ul);
        hi[j] = uh;
        lo[j] = ul;
    }
}

// ---------------------------------------------------------------------------
// mma.sync split-bf16 TN GEMM (frozen, R13-best)
// ---------------------------------------------------------------------------
template<int MT, int NT, int NWM, int MINB, int NST>
__global__ void __launch_bounds__(256, MINB)
gemm_mma_bf16x3(const __nv_bfloat16* __restrict__ aHi, const __nv_bfloat16* __restrict__ aLo,
                const __nv_bfloat16* __restrict__ wHi, const __nv_bfloat16* __restrict__ wLo,
                const float* __restrict__ bias, const float* __restrict__ addin,
                float* __restrict__ C, int M)
{
    constexpr int NWN = 8 / NWM;
    constexpr int BM  = NWM * MT * 16;
    constexpr int BN  = NWN * NT * 8;
    constexpr int A_B = BM * 128;
    constexpr int W_B = BN * 128;
    constexpr int STG = 2 * A_B + 2 * W_B;

    extern __shared__ __align__(1024) char smem[];
    const uint32_t sb = smem_u32(smem);
    const int tid = threadIdx.x, lane = tid & 31, wid = tid >> 5;
    const int wm = wid / NWN, wn = wid % NWN;
    const int m0 = blockIdx.x * BM, n0 = blockIdx.y * BN;

    auto stage = [&](int c) {
        const uint32_t base = sb + (c % NST) * STG;
        const int kt = c * 64;
        #pragma unroll
        for (int l = 0; l < BM * 8 / 256; l++) {
            int idx = tid + l * 256;
            int r = idx >> 3, cc = idx & 7;
            uint32_t so = swz((uint32_t)(r * 128 + cc * 16));
            int row = m0 + r;
            int sz  = (row < M) ? 16 : 0;
            size_t off = (size_t)(sz ? row : 0) * MD + kt + cc * 8;
            cp16(base + so,       aHi + off, sz);
            cp16(base + A_B + so, aLo + off, sz);
        }
        #pragma unroll
        for (int l = 0; l < BN * 8 / 256; l++) {
            int idx = tid + l * 256;
            int r = idx >> 3, cc = idx & 7;
            uint32_t so = swz((uint32_t)(r * 128 + cc * 16));
            size_t off = (size_t)(n0 + r) * MD + kt + cc * 8;
            cp16(base + 2 * A_B + so,       wHi + off, 16);
            cp16(base + 2 * A_B + W_B + so, wLo + off, 16);
        }
        asm volatile("cp.async.commit_group;" ::: "memory");
    };

    float acc[MT][NT][4];
    #pragma unroll
    for (int i = 0; i < MT; i++)
        #pragma unroll
        for (int j = 0; j < NT; j++)
            #pragma unroll
            for (int q = 0; q < 4; q++) acc[i][j][q] = 0.f;

    #pragma unroll
    for (int s = 0; s < NST; s++) stage(s);

    for (int c = 0; c < NCH; c++) {
        asm volatile("cp.async.wait_group %0;" :: "n"(NST - 1) : "memory");
        __syncthreads();
        const uint32_t base = sb + (c % NST) * STG;
        const uint32_t Ah = base, Al = base + A_B;
        const uint32_t Wh = base + 2 * A_B, Wl = Wh + W_B;

        #pragma unroll
        for (int ks = 0; ks < 4; ks++) {
            uint32_t bh[NT][2], bl[NT][2];
            #pragma unroll
            for (int ntp = 0; ntp < NT / 2; ntp++) {
                uint32_t so = swz((uint32_t)((wn * (NT * 8) + ntp * 16
                                              + ((lane >> 4) & 1) * 8 + (lane & 7)) * 128
                                             + ks * 32 + ((lane >> 3) & 1) * 16));
                ldsm_x4(bh[2 * ntp][0], bh[2 * ntp][1],
                        bh[2 * ntp + 1][0], bh[2 * ntp + 1][1], Wh + so);
                ldsm_x4(bl[2 * ntp][0], bl[2 * ntp][1],
                        bl[2 * ntp + 1][0], bl[2 * ntp + 1][1], Wl + so);
            }
            uint32_t ah[MT][4], al[MT][4];
            #pragma unroll
            for (int mt = 0; mt < MT; mt++) {
                uint32_t so = swz((uint32_t)((wm * (MT * 16) + mt * 16 + (lane & 15)) * 128
                                             + ks * 32 + (lane >> 4) * 16));
                ldsm_x4(ah[mt][0], ah[mt][1], ah[mt][2], ah[mt][3], Ah + so);
                ldsm_x4(al[mt][0], al[mt][1], al[mt][2], al[mt][3], Al + so);
            }
            #pragma unroll
            for (int mt = 0; mt < MT; mt++)
                #pragma unroll
                for (int nt = 0; nt < NT; nt++)
                    mma16816(acc[mt][nt], ah[mt], bh[nt]);
            #pragma unroll
            for (int mt = 0; mt < MT; mt++)
                #pragma unroll
                for (int nt = 0; nt < NT; nt++)
                    mma16816(acc[mt][nt], ah[mt], bl[nt]);
            #pragma unroll
            for (int mt = 0; mt < MT; mt++)
                #pragma unroll
                for (int nt = 0; nt < NT; nt++)
                    mma16816(acc[mt][nt], al[mt], bh[nt]);
        }
        __syncthreads();
        if (c + NST < NCH) stage(c + NST);
        else asm volatile("cp.async.commit_group;" ::: "memory");
    }
    asm volatile("cp.async.wait_group 0;" ::: "memory");

    #pragma unroll
    for (int mt = 0; mt < MT; mt++) {
        #pragma unroll
        for (int half = 0; half < 2; half++) {
            int row = m0 + wm * (MT * 16) + mt * 16 + half * 8 + (lane >> 2);
            if (row >= M) continue;
            #pragma unroll
            for (int nt = 0; nt < NT; nt++) {
                int col = n0 + wn * (NT * 8) + nt * 8 + (lane & 3) * 2;
                float2 v;
                v.x = acc[mt][nt][half * 2 + 0];
                v.y = acc[mt][nt][half * 2 + 1];
                float2 bv = *(const float2*)(bias + col);
                v.x += bv.x; v.y += bv.y;
                if (addin) {
                    float2 h = *(const float2*)(addin + (size_t)row * H_ + col);
                    v.x += h.x; v.y += h.y;
                }
                *(float2*)(C + (size_t)row * H_ + col) = v;
            }
        }
    }
}

// ---------------------------------------------------------------------------
// scores: raw scores, mlo read exactly once (R13 version, 32-t tiles).
// ---------------------------------------------------------------------------
__global__ void __launch_bounds__(256)
scores_kernel(const float* __restrict__ mlo, const float* __restrict__ hiddens,
              const float* __restrict__ W_rect, float* __restrict__ sc)
{
    extern __shared__ __align__(16) float s_hid[];    // [32][H_] = 96 KB

    const int pt = blockIdx.x;        // 0..6
    const int t0 = blockIdx.y * 32;   // 0 or 32
    const int b  = blockIdx.z;
    const int tid = threadIdx.x, lane = tid & 31, warp = tid >> 5;

    {
        const float4* src = (const float4*)(hiddens + (size_t)(b * T_ + t0) * H_);
        float4* dst = (float4*)s_hid;
        for (int i = tid; i < 32 * H_ / 4; i += 256) dst[i] = src[i];
    }

    float4 wr[6];
    #pragma unroll
    for (int q = 0; q < 6; q++) wr[q] = ((const float4*)W_rect)[q * 32 + lane];

    const int nrows = (warp < 4) ? 4 : 3;
    float4 x[4][6];
    #pragma unroll
    for (int r = 0; r < 4; r++) {
        if (r >= nrows) break;
        const int p = pt * 28 + warp + r * 8;
        const float4* mp = (const float4*)(mlo + (size_t)(b * P_ + p) * H_);
        #pragma unroll
        for (int q = 0; q < 6; q++) x[r][q] = mp[q * 32 + lane];
    }
    __syncthreads();

    for (int t = 0; t < 32; t++) {
        float4 hd[6];
        const float4* hp = (const float4*)(s_hid + t * H_);
        #pragma unroll
        for (int q = 0; q < 6; q++) hd[q] = hp[q * 32 + lane];

        float acc[4] = {};
        #pragma unroll
        for (int r = 0; r < 4; r++) {
            if (r >= nrows) break;
            float a = 0.f;
            #pragma unroll
            for (int q = 0; q < 6; q++) {
                a += fmaxf(x[r][q].x + hd[q].x, 0.f) * wr[q].x
                   + fmaxf(x[r][q].y + hd[q].y, 0.f) * wr[q].y
                   + fmaxf(x[r][q].z + hd[q].z, 0.f) * wr[q].z
                   + fmaxf(x[r][q].w + hd[q].w, 0.f) * wr[q].w;
            }
            acc[r] = a;
        }
        #pragma unroll
        for (int r = 0; r < 4; r++) {
            if (r >= nrows) break;
            float v = acc[r];
            #pragma unroll
            for (int o = 16; o > 0; o >>= 1) v += __shfl_xor_sync(0xffffffffu, v, o);
            if (lane == 0)
                sc[(size_t)(b * T_ + t0 + t) * P_ + pt * 28 + warp + r * 8] = v;
        }
    }
}

// ---------------------------------------------------------------------------
// softmax over p: writes attn fp32 (output) + bf16 hi/lo (zero-padded to KP).
// Warp per (b,t)-row; 64 blocks x 256.
// ---------------------------------------------------------------------------
__global__ void __launch_bounds__(256)
softmax_kernel(const float* __restrict__ sc, float* __restrict__ attn_out,
               __nv_bfloat16* __restrict__ atH, __nv_bfloat16* __restrict__ atL)
{
    const int row = blockIdx.x * 8 + (threadIdx.x >> 5);   // 0..511
    const int lane = threadIdx.x & 31;
    const float* sp = sc + (size_t)row * P_;

    float v[7];
    float mx = -1e30f;
    #pragma unroll
    for (int i = 0; i < 7; i++) {
        int p = lane + i * 32;
        v[i] = (p < P_) ? sp[p] : -1e30f;
        mx = fmaxf(mx, v[i]);
    }
    #pragma unroll
    for (int o = 16; o > 0; o >>= 1) mx = fmaxf(mx, __shfl_xor_sync(0xffffffffu, mx, o));
    float sm = 0.f;
    #pragma unroll
    for (int i = 0; i < 7; i++) {
        v[i] = expf(v[i] - mx);
        sm += v[i];
    }
    #pragma unroll
    for (int o = 16; o > 0; o >>= 1) sm += __shfl_xor_sync(0xffffffffu, sm, o);
    float inv = 1.f / sm;
    #pragma unroll
    for (int i = 0; i < 7; i++) {
        int p = lane + i * 32;
        if (p < P_) {
            float a = v[i] * inv;
            if (attn_out) attn_out[(size_t)row * P_ + p] = a;
            __nv_bfloat16 h = __float2bfloat16(a);
            __nv_bfloat16 l = __float2bfloat16(a - __bfloat162float(h));
            atH[(size_t)row * KP + p] = h;
            atL[(size_t)row * KP + p] = l;
        } else if (p < KP) {
            atH[(size_t)row * KP + p] = __float2bfloat16(0.f);
            atL[(size_t)row * KP + p] = __float2bfloat16(0.f);
        }
    }
}

// ---------------------------------------------------------------------------
// ctx via mma.sync: ctx[b] = attn[b] @ fm[b] using split-bf16 x3.
// A = attn hi/lo [64 x KP] (smem, 432B rows). B = fm hi/lo chunks staged
// [k=p rows][64 n] (SW128), loaded with ldmatrix.x4.trans (n-major B).
// Grid (MD/64, B_) = 256 blocks, 256 threads = 8 warps (2m x 4n), MT=2, NT=2.
// ---------------------------------------------------------------------------
constexpr int NKC     = KP / 16;          // 13
constexpr int A_ROWB  = 432;              // KP*2=416 padded to 432 (27x16B)
constexpr int A_MATB  = 64 * A_ROWB;      // 27648
constexpr int FM_MATB = 16 * 128;         // 2048 (16 p-rows x 128B)
constexpr int FM_BUFB = 2 * FM_MATB;      // hi+lo
constexpr int CTXM_SMEM = 2 * A_MATB + 2 * FM_BUFB;   // 63,488

__global__ void __launch_bounds__(256, 3)
ctx_mma_kernel(const __nv_bfloat16* __restrict__ atH, const __nv_bfloat16* __restrict__ atL,
               const __nv_bfloat16* __restrict__ fmH, const __nv_bfloat16* __restrict__ fmL,
               __nv_bfloat16* __restrict__ cxh, __nv_bfloat16* __restrict__ cxl)
{
    extern __shared__ __align__(1024) char smem[];
    const uint32_t sb = smem_u32(smem);
    const uint32_t fm_base = sb + 2 * A_MATB;

    const int n0 = blockIdx.x * 64;
    const int b  = blockIdx.y;
    const int tid = threadIdx.x, lane = tid & 31, wid = tid >> 5;
    const int wm = wid >> 2, wn = wid & 3;      // 2 x 4 warps

    // --- A fill: attn hi/lo [64][KP] -> smem rows of 432B (once) ---
    for (int i = tid; i < 3328; i += 256) {
        int mat = i >= 1664;
        int j = mat ? i - 1664 : i;
        int t = j / 26, seg = j % 26;
        const __nv_bfloat16* src = (mat ? atL : atH) + (size_t)(b * T_ + t) * KP + seg * 8;
        cp16(sb + mat * A_MATB + t * A_ROWB + seg * 16, src, 16);
    }
    asm volatile("cp.async.commit_group;" ::: "memory");

    // --- fm chunk staging: 16 p-rows x 64 n (hi+lo), double-buffered ---
    // FIX (R15 bug): fm row index must include the batch offset b*P_.
    auto stage = [&](int ch) {
        const uint32_t base = fm_base + (ch & 1) * FM_BUFB;
        int mat = tid >> 7;               // 0=hi, 1=lo
        int r   = (tid >> 3) & 15;        // p-row in chunk
        int c   = tid & 7;                // 16B segment
        int p   = ch * 16 + r;
        int sz  = (p < P_) ? 16 : 0;
        const __nv_bfloat16* src = (mat ? fmL : fmH)
                                   + (size_t)(sz ? (b * P_ + p) : 0) * MD + n0 + c * 8;
        cp16(base + mat * FM_MATB + swz((uint32_t)(r * 128 + c * 16)), src, sz);
        asm volatile("cp.async.commit_group;" ::: "memory");
    };

    stage(0);
    stage(1);

    float acc[2][2][4];
    #pragma unroll
    for (int i = 0; i < 2; i++)
        #pragma unroll
        for (int j = 0; j < 2; j++)
            #pragma unroll
            for (int q = 0; q < 4; q++) acc[i][j][q] = 0.f;

    for (int ch = 0; ch < NKC; ch++) {
        asm volatile("cp.async.wait_group 1;" ::: "memory");
        __syncthreads();
        const uint32_t Wh = fm_base + (ch & 1) * FM_BUFB;
        const uint32_t Wl = Wh + FM_MATB;

        // B fragments via ldmatrix.trans (n-major B): groups g = (npair<<1)|khalf
        uint32_t bso = swz((uint32_t)((((lane >> 3) & 1) * 8 + (lane & 7)) * 128
                                      + wn * 32 + (lane >> 4) * 16));
        uint32_t bh[2][2], bl[2][2];
        ldsm_x4t(bh[0][0], bh[0][1], bh[1][0], bh[1][1], Wh + bso);
        ldsm_x4t(bl[0][0], bl[0][1], bl[1][0], bl[1][1], Wl + bso);

        // A fragments (no trans)
        uint32_t ah[2][4], al[2][4];
        #pragma unroll
        for (int mt = 0; mt < 2; mt++) {
            uint32_t aso = (uint32_t)((wm * 32 + mt * 16 + (lane & 15)) * A_ROWB
                                      + ch * 32 + (lane >> 4) * 16);
            ldsm_x4(ah[mt][0], ah[mt][1], ah[mt][2], ah[mt][3], sb + aso);
            ldsm_x4(al[mt][0], al[mt][1], al[mt][2], al[mt][3], sb + A_MATB + aso);
        }

        #pragma unroll
        for (int mt = 0; mt < 2; mt++)
            #pragma unroll
            for (int nt = 0; nt < 2; nt++)
                mma16816(acc[mt][nt], ah[mt], bh[nt]);
        #pragma unroll
        for (int mt = 0; mt < 2; mt++)
            #pragma unroll
            for (int nt = 0; nt < 2; nt++)
                mma16816(acc[mt][nt], ah[mt], bl[nt]);
        #pragma unroll
        for (int mt = 0; mt < 2; mt++)
            #pragma unroll
            for (int nt = 0; nt < 2; nt++)
                mma16816(acc[mt][nt], al[mt], bh[nt]);

        __syncthreads();
        if (ch + 2 < NKC) stage(ch + 2);
        else asm volatile("cp.async.commit_group;" ::: "memory");
    }
    asm volatile("cp.async.wait_group 0;" ::: "memory");

    // epilogue: split fp32 acc -> cx hi/lo bf16
    #pragma unroll
    for (int mt = 0; mt < 2; mt++) {
        #pragma unroll
        for (int half = 0; half < 2; half++) {
            int t = wm * 32 + mt * 16 + half * 8 + (lane >> 2);
            #pragma unroll
            for (int nt = 0; nt < 2; nt++) {
                int col = n0 + wn * 16 + nt * 8 + (lane & 3) * 2;
                float vx = acc[mt][nt][half * 2 + 0];
                float vy = acc[mt][nt][half * 2 + 1];
                __nv_bfloat16 hx = __float2bfloat16(vx), hy = __float2bfloat16(vy);
                __nv_bfloat16 lx = __float2bfloat16(vx - __bfloat162float(hx));
                __nv_bfloat16 ly = __float2bfloat16(vy - __bfloat162float(hy));
                __nv_bfloat162 h2 = __halves2bfloat162(hx, hy);
                __nv_bfloat162 l2 = __halves2bfloat162(lx, ly);
                size_t off = (size_t)(b * T_ + t) * MD + col;
                *(uint32_t*)(cxh + off) = *(uint32_t*)&h2;
                *(uint32_t*)(cxl + off) = *(uint32_t*)&l2;
            }
        }
    }
}

// ---------------------------------------------------------------------------
// launch
// ---------------------------------------------------------------------------
extern "C" void kernel_launch(void* const* d_in, const int* in_sizes, int n_in,
                              void* d_out, int out_size)
{
    const float* maps    = (const float*)d_in[0];
    const float* hiddens = (const float*)d_in[1];
    const float* W_map   = (const float*)d_in[2];
    const float* b_map   = (const float*)d_in[3];
    const float* W_final = (const float*)d_in[4];
    const float* b_final = (const float*)d_in[5];
    const float* W_rect  = (const float*)d_in[6];
    // d_in[7] = b_rect : softmax-invariant, unused.

    float* out = (float*)d_out;       // [out (BT,H) | attn (BT,P)]

    void *v0, *v1, *v2, *v3, *v4, *v5, *v6, *v7, *v8, *v9, *vA, *vB;
    cudaGetSymbolAddress(&v0, g_mlo);
    cudaGetSymbolAddress(&v1, g_sc);
    cudaGetSymbolAddress(&v2, g_a_hi);  cudaGetSymbolAddress(&v3, g_a_lo);
    cudaGetSymbolAddress(&v4, g_wm_hi); cudaGetSymbolAddress(&v5, g_wm_lo);
    cudaGetSymbolAddress(&v6, g_wf_hi); cudaGetSymbolAddress(&v7, g_wf_lo);
    cudaGetSymbolAddress(&v8, g_cx_hi); cudaGetSymbolAddress(&v9, g_cx_lo);
    cudaGetSymbolAddress(&vA, g_at_hi); cudaGetSymbolAddress(&vB, g_at_lo);
    float* p_mlo = (float*)v0;
    float* p_sc  = (float*)v1;
    __nv_bfloat16 *aHi = (__nv_bfloat16*)v2, *aLo = (__nv_bfloat16*)v3;
    __nv_bfloat16 *wmHi = (__nv_bfloat16*)v4, *wmLo = (__nv_bfloat16*)v5;
    __nv_bfloat16 *wfHi = (__nv_bfloat16*)v6, *wfLo = (__nv_bfloat16*)v7;
    __nv_bfloat16 *cxHi = (__nv_bfloat16*)v8, *cxLo = (__nv_bfloat16*)v9;
    __nv_bfloat16 *atHi = (__nv_bfloat16*)vA, *atLo = (__nv_bfloat16*)vB;

    float* attn = (out_size >= BT * H_ + BT * P_) ? out + (size_t)BT * H_ : nullptr;

    constexpr int SMEM_G1 = 2 * (2 * 64 * 128 + 2 * 64 * 128);   // 65536
    constexpr int SMEM_G4 = 2 * (2 * 64 * 128 + 2 * 32 * 128);   // 49152
    constexpr int SMEM_SC = 32 * H_ * 4;                         // 98304
    cudaFuncSetAttribute((const void*)gemm_mma_bf16x3<2, 2, 2, 3, 2>,
                         cudaFuncAttributeMaxDynamicSharedMemorySize, SMEM_G1);
    cudaFuncSetAttribute((const void*)gemm_mma_bf16x3<1, 2, 4, 3, 2>,
                         cudaFuncAttributeMaxDynamicSharedMemorySize, SMEM_G4);
    cudaFuncSetAttribute(scores_kernel,
                         cudaFuncAttributeMaxDynamicSharedMemorySize, SMEM_SC);
    cudaFuncSetAttribute(ctx_mma_kernel,
                         cudaFuncAttributeMaxDynamicSharedMemorySize, CTXM_SMEM);

    // 1. fused split-convert of maps, W_map, W_final to bf16 hi/lo
    convert_split_all<<<1184, 256>>>((const float4*)maps, (const float4*)W_map,
                                     (const float4*)W_final,
                                     (uint2*)aHi, (uint2*)aLo,
                                     (uint2*)wmHi, (uint2*)wmLo,
                                     (uint2*)wfHi, (uint2*)wfLo);

    // 2. mlo = maps @ W_map^T + b_map   (25 x 12 = 300 blocks, 3 CTAs/SM)
    gemm_mma_bf16x3<2, 2, 2, 3, 2><<<dim3((BP + 63) / 64, H_ / 64), 256, SMEM_G1>>>(
        aHi, aLo, wmHi, wmLo, b_map, nullptr, p_mlo, BP);

    // 3. raw scores (7 x 2 x 8 = 112 blocks)
    scores_kernel<<<dim3(7, 2, B_), 256, SMEM_SC>>>(p_mlo, hiddens, W_rect, p_sc);

    // 4. softmax -> attn fp32 + attn bf16 hi/lo (64 blocks)
    softmax_kernel<<<BT / 8, 256>>>(p_sc, attn, atHi, atLo);

    // 5. ctx = attn @ fm via tensor cores (32 x 8 = 256 blocks, 3 CTAs/SM)
    ctx_mma_kernel<<<dim3(MD / 64, B_), 256, CTXM_SMEM>>>(
        atHi, atLo, aHi, aLo, cxHi, cxLo);

    // 6. out = ctx @ W_final^T + b_final + hiddens   (8 x 24 = 192 blocks)
    gemm_mma_bf16x3<1, 2, 4, 3, 2><<<dim3(BT / 64, H_ / 32), 256, SMEM_G4>>>(
        cxHi, cxLo, wfHi, wfLo, b_final, hiddens, out, BT);
}